// round 7
// baseline (speedup 1.0000x reference)
#include <cuda_runtime.h>

// ---------------- scratch (device globals: no allocations allowed) ----------------
__device__ float g_h1[67108864];   // [32,128,128,128] encoder hidden
__device__ float g_z [ 8388608];   // [32,64,64,64]    pre-quant latents
__device__ float g_zq[ 8388608];   // [32,64,64,64]    straight-through latents
__device__ float g_d1[67108864];   // [32,128,128,128] decoder hidden
__device__ int   g_idx[131072];    // [32,4096]        code indices

// =====================================================================
// conv1: x[32,3,256,256] -> h1[32,128,128,128], k4 s2 p1, bias + ReLU
// =====================================================================
__global__ __launch_bounds__(256) void conv1_kernel(const float* __restrict__ x,
                                                    const float* __restrict__ w,
                                                    const float* __restrict__ bias) {
    __shared__ float w_s[6144];       // [oc][c*16+kh*4+kw] == global layout
    __shared__ float b_s[128];
    __shared__ float p_s[3 * 34 * 34];
    const int tid = threadIdx.x;
    const int b  = blockIdx.z;
    const int ty = blockIdx.y, tx = blockIdx.x;

    for (int i = tid; i < 6144; i += 256) w_s[i] = w[i];
    if (tid < 128) b_s[tid] = bias[tid];

    const int iy0 = ty * 32 - 1, ix0 = tx * 32 - 1;
    for (int i = tid; i < 3468; i += 256) {
        int c = i / 1156, rem = i % 1156, r = rem / 34, cl = rem % 34;
        int iy = iy0 + r, ix = ix0 + cl;
        float v = 0.f;
        if (iy >= 0 && iy < 256 && ix >= 0 && ix < 256)
            v = x[((b * 3 + c) * 256 + iy) * 256 + ix];
        p_s[i] = v;
    }
    __syncthreads();

    const int lpy = tid >> 4, lpx = tid & 15;
    float xr[48];
#pragma unroll
    for (int c = 0; c < 3; c++)
#pragma unroll
        for (int kh = 0; kh < 4; kh++)
#pragma unroll
            for (int kw = 0; kw < 4; kw++)
                xr[c * 16 + kh * 4 + kw] = p_s[c * 1156 + (2 * lpy + kh) * 34 + 2 * lpx + kw];

    const int oy = ty * 16 + lpy, ox = tx * 16 + lpx;
    float* outp = &g_h1[(((long)b * 128) * 128 + oy) * 128 + ox];
#pragma unroll 2
    for (int oc = 0; oc < 128; oc++) {
        const float4* wr = (const float4*)(w_s + oc * 48);
        float a0 = b_s[oc], a1 = 0.f;
#pragma unroll
        for (int j = 0; j < 12; j += 2) {
            float4 w0 = wr[j], w1 = wr[j + 1];
            a0 += xr[4*j+0]*w0.x + xr[4*j+1]*w0.y + xr[4*j+2]*w0.z + xr[4*j+3]*w0.w;
            a1 += xr[4*j+4]*w1.x + xr[4*j+5]*w1.y + xr[4*j+6]*w1.z + xr[4*j+7]*w1.w;
        }
        outp[(long)oc * 128 * 128] = fmaxf(a0 + a1, 0.f);
    }
}

// =====================================================================
// conv2: h1[32,128,128,128] -> z[32,64,64,64], k4 s2 p1, bias (no ReLU)
// =====================================================================
__global__ __launch_bounds__(256) void conv2_kernel(const float* __restrict__ w,
                                                    const float* __restrict__ bias) {
    __shared__ float p_s[8 * 324];    // [ic8][18][18]
    __shared__ float w_s[8192];       // [(ic*16+t)][oc64]
    __shared__ float b_s[64];
    const int tid = threadIdx.x;
    const int b   = blockIdx.z;
    const int oy0 = blockIdx.y * 8, ox0 = blockIdx.x * 8;
    const int iy0 = oy0 * 2 - 1, ix0 = ox0 * 2 - 1;
    if (tid < 64) b_s[tid] = bias[tid];

    const int ocq = tid & 15, pq = tid >> 4;
    const int qy = pq >> 2, qx = pq & 3;
    float a00[4] = {}, a01[4] = {}, a10[4] = {}, a11[4] = {};

    for (int cc = 0; cc < 16; cc++) {
        const int icb = cc * 8;
        __syncthreads();
        for (int i = tid; i < 2592; i += 256) {
            int lic = i / 324, rem = i % 324, r = rem / 18, cl = rem % 18;
            int iy = iy0 + r, ix = ix0 + cl;
            float v = 0.f;
            if (iy >= 0 && iy < 128 && ix >= 0 && ix < 128)
                v = g_h1[(((long)b * 128 + icb + lic) * 128 + iy) * 128 + ix];
            p_s[i] = v;
        }
        for (int i = tid; i < 8192; i += 256) {
            int oc = i & 63, t = (i >> 6) & 15, lic = i >> 10;
            w_s[i] = w[((long)oc * 128 + icb + lic) * 16 + t];
        }
        __syncthreads();
        for (int lic = 0; lic < 8; lic++) {
            const float* pb = p_s + lic * 324;
#pragma unroll
            for (int kh = 0; kh < 4; kh++) {
#pragma unroll
                for (int kw = 0; kw < 4; kw++) {
                    float4 wv = *(const float4*)(w_s + (lic * 16 + kh * 4 + kw) * 64 + ocq * 4);
                    const float* pr0 = pb + (4 * qy + kh) * 18 + 4 * qx + kw;
                    const float* pr1 = pb + (4 * qy + 2 + kh) * 18 + 4 * qx + kw;
                    float x00 = pr0[0], x01 = pr0[2], x10 = pr1[0], x11 = pr1[2];
                    a00[0] += x00*wv.x; a00[1] += x00*wv.y; a00[2] += x00*wv.z; a00[3] += x00*wv.w;
                    a01[0] += x01*wv.x; a01[1] += x01*wv.y; a01[2] += x01*wv.z; a01[3] += x01*wv.w;
                    a10[0] += x10*wv.x; a10[1] += x10*wv.y; a10[2] += x10*wv.z; a10[3] += x10*wv.w;
                    a11[0] += x11*wv.x; a11[1] += x11*wv.y; a11[2] += x11*wv.z; a11[3] += x11*wv.w;
                }
            }
        }
    }
    __syncthreads();
#pragma unroll
    for (int o = 0; o < 4; o++) {
        int oc = ocq * 4 + o;
        float bb = b_s[oc];
        w_s[oc * 64 + (2 * qy    ) * 8 + 2 * qx    ] = a00[o] + bb;
        w_s[oc * 64 + (2 * qy    ) * 8 + 2 * qx + 1] = a01[o] + bb;
        w_s[oc * 64 + (2 * qy + 1) * 8 + 2 * qx    ] = a10[o] + bb;
        w_s[oc * 64 + (2 * qy + 1) * 8 + 2 * qx + 1] = a11[o] + bb;
    }
    __syncthreads();
    for (int i = tid; i < 4096; i += 256) {
        int oc = i >> 6, rem = i & 63, y = rem >> 3, xx = rem & 7;
        g_z[(((long)b * 64 + oc) * 64 + oy0 + y) * 64 + ox0 + xx] = w_s[i];
    }
}

// =====================================================================
// XLA-style row reduction of 64 squares: lane i gets elements {i, i+32},
// then a pairwise shuffle tree (offsets 16,8,4,2,1). Emulated in-thread
// with strict fp32 rounding (immune to fast-math).
// =====================================================================
__device__ __forceinline__ float xla_sumsq64(const float* __restrict__ a) {
    float s[32];
#pragma unroll
    for (int j = 0; j < 32; j++)
        s[j] = __fadd_rn(__fmul_rn(a[j], a[j]), __fmul_rn(a[j + 32], a[j + 32]));
#pragma unroll
    for (int off = 16; off >= 1; off >>= 1)
#pragma unroll
        for (int j = 0; j < 16; j++)
            if (j < off) s[j] = __fadd_rn(s[j], s[j + off]);
    return s[0];
}

// =====================================================================
// VQ argmin: vector n = (c*64+h) is z[b,c,h,0:64] (contiguous).
// Replicates reference numerics: d = fl(fl(zz - 2*dot) + cc),
// zz/cc via XLA warp-tree order, dot via sequential fp32 FMA (cublas
// sgemm order). Strict < over ascending k = first-min tie-break.
// =====================================================================
__global__ __launch_bounds__(256) void vq_argmin_kernel(const float* __restrict__ cb) {
    extern __shared__ float sm[];
    float* cb_s = sm;            // 32768
    float* cn_s = sm + 32768;    // 512
    const int tid = threadIdx.x;
    for (int i = tid; i < 32768; i += 256) cb_s[i] = cb[i];
    __syncthreads();
    for (int k = tid; k < 512; k += 256)
        cn_s[k] = xla_sumsq64(cb_s + k * 64);
    __syncthreads();

    const int v = blockIdx.x * 256 + tid;        // v = b*4096 + n
    const float* zp = g_z + (long)v * 64;
    float zr[64];
#pragma unroll
    for (int j = 0; j < 16; j++) {
        float4 t = *(const float4*)(zp + 4 * j);
        zr[4*j] = t.x; zr[4*j+1] = t.y; zr[4*j+2] = t.z; zr[4*j+3] = t.w;
    }
    const float zz = xla_sumsq64(zr);

    float best = 3.0e38f; int bi = 0;
    for (int k = 0; k < 512; k += 4) {
        const float* r0 = cb_s + (k    ) * 64;
        const float* r1 = cb_s + (k + 1) * 64;
        const float* r2 = cb_s + (k + 2) * 64;
        const float* r3 = cb_s + (k + 3) * 64;
        float d0 = 0.f, d1 = 0.f, d2 = 0.f, d3 = 0.f;
#pragma unroll
        for (int j = 0; j < 64; j++) {       // sequential k-order per code (cublas)
            d0 = __fmaf_rn(zr[j], r0[j], d0);
            d1 = __fmaf_rn(zr[j], r1[j], d1);
            d2 = __fmaf_rn(zr[j], r2[j], d2);
            d3 = __fmaf_rn(zr[j], r3[j], d3);
        }
        float t0 = __fadd_rn(__fadd_rn(zz, -__fmul_rn(2.f, d0)), cn_s[k    ]);
        float t1 = __fadd_rn(__fadd_rn(zz, -__fmul_rn(2.f, d1)), cn_s[k + 1]);
        float t2 = __fadd_rn(__fadd_rn(zz, -__fmul_rn(2.f, d2)), cn_s[k + 2]);
        float t3 = __fadd_rn(__fadd_rn(zz, -__fmul_rn(2.f, d3)), cn_s[k + 3]);
        if (t0 < best) { best = t0; bi = k;     }
        if (t1 < best) { best = t1; bi = k + 1; }
        if (t2 < best) { best = t2; bi = k + 2; }
        if (t3 < best) { best = t3; bi = k + 3; }
    }
    g_idx[v] = bi;
}

// =====================================================================
// scatter + straight-through: zq[b,e,hh,ww] = fl(z + fl(cb[idx[b,hh*64+ww]][e] - z))
// =====================================================================
__global__ __launch_bounds__(256) void vq_gather_kernel(const float* __restrict__ cb) {
    const int tid = threadIdx.x;
    const int b = blockIdx.x >> 6, hh = blockIdx.x & 63;
    __shared__ int ids[64];
    if (tid < 64) ids[tid] = g_idx[b * 4096 + hh * 64 + tid];
    __syncthreads();
    const int ww = tid & 63, eg = tid >> 6;
    const int id = ids[ww];
#pragma unroll
    for (int it = 0; it < 16; it++) {
        int e = eg * 16 + it;
        long zo = (((long)b * 64 + e) * 64 + hh) * 64 + ww;
        float zv = g_z[zo];
        g_zq[zo] = __fadd_rn(zv, __fadd_rn(cb[id * 64 + e], -zv));
    }
}

// =====================================================================
// deconv1: zq[32,64,64,64] -> d1[32,128,128,128], input-dilated corr, ReLU
// =====================================================================
__global__ __launch_bounds__(256) void deconv1_kernel(const float* __restrict__ w,
                                                      const float* __restrict__ bias) {
    __shared__ float p_s[16 * 100];   // [ic16][10][10]
    __shared__ float w_s[4096];       // [(ic*16+t)][oc16]
    __shared__ float b_s[16];
    const int tid = threadIdx.x;
    const int bz = blockIdx.z;
    const int b = bz >> 3, OC0 = (bz & 7) * 16;
    const int y0 = blockIdx.y * 16, x0 = blockIdx.x * 16;
    const int ihb = (y0 >> 1) - 1, iwb = (x0 >> 1) - 1;
    if (tid < 16) b_s[tid] = bias[OC0 + tid];

    const int oq = tid & 3, pq = tid >> 2;
    const int qy = pq >> 3, qx = pq & 7;
    float acc[4][4] = {};

    for (int cc = 0; cc < 4; cc++) {
        const int icb = cc * 16;
        __syncthreads();
        for (int i = tid; i < 1600; i += 256) {
            int lic = i / 100, rem = i % 100, r = rem / 10, cl = rem % 10;
            int ih = ihb + r, iw = iwb + cl;
            float v = 0.f;
            if (ih >= 0 && ih < 64 && iw >= 0 && iw < 64)
                v = g_zq[(((long)b * 64 + icb + lic) * 64 + ih) * 64 + iw];
            p_s[i] = v;
        }
        for (int i = tid; i < 4096; i += 256) {
            int oc = i & 15, t = (i >> 4) & 15, lic = i >> 8;
            w_s[i] = w[((long)(OC0 + oc) * 64 + icb + lic) * 16 + t];
        }
        __syncthreads();
        for (int lic = 0; lic < 16; lic++) {
            float x3[3][3];
#pragma unroll
            for (int r = 0; r < 3; r++)
#pragma unroll
                for (int c = 0; c < 3; c++)
                    x3[r][c] = p_s[lic * 100 + (qy + r) * 10 + qx + c];
#pragma unroll
            for (int kh = 0; kh < 4; kh++) {
#pragma unroll
                for (int kw = 0; kw < 4; kw++) {
                    const int RRh = (kh + (kh & 1)) >> 1;   // {0,1,1,2}
                    const int RRw = (kw + (kw & 1)) >> 1;
                    float xv = x3[RRh][RRw];
                    float4 wv = *(const float4*)(w_s + (lic * 16 + kh * 4 + kw) * 16 + oq * 4);
                    const int p = (kh & 1) * 2 + (kw & 1);
                    acc[p][0] += xv * wv.x; acc[p][1] += xv * wv.y;
                    acc[p][2] += xv * wv.z; acc[p][3] += xv * wv.w;
                }
            }
        }
    }
    __syncthreads();
#pragma unroll
    for (int dy = 0; dy < 2; dy++)
#pragma unroll
        for (int dx = 0; dx < 2; dx++)
#pragma unroll
            for (int o = 0; o < 4; o++) {
                int oc = oq * 4 + o;
                w_s[oc * 256 + (2 * qy + dy) * 16 + 2 * qx + dx] =
                    fmaxf(acc[dy * 2 + dx][o] + b_s[oc], 0.f);
            }
    __syncthreads();
    for (int i = tid; i < 4096; i += 256) {
        int oc = i >> 8, rem = i & 255, y = rem >> 4, xx = rem & 15;
        g_d1[(((long)b * 128 + OC0 + oc) * 128 + y0 + y) * 128 + x0 + xx] = w_s[i];
    }
}

// =====================================================================
// deconv2: d1[32,128,128,128] -> out[32,3,256,256], bias (no ReLU)
// =====================================================================
__global__ __launch_bounds__(256) void deconv2_kernel(const float* __restrict__ w,
                                                      const float* __restrict__ bias,
                                                      float* __restrict__ out) {
    __shared__ float p_s[16 * 324];   // [ic16][18][18]
    __shared__ float w_s[1024];       // [(ic*16+t)][4] (3 used)
    const int tid = threadIdx.x;
    const int b = blockIdx.z;
    const int y0 = blockIdx.y * 32, x0 = blockIdx.x * 32;
    const int ihb = (y0 >> 1) - 1, iwb = (x0 >> 1) - 1;
    const int qy = tid >> 4, qx = tid & 15;
    float acc[4][3] = {};

    for (int cc = 0; cc < 8; cc++) {
        const int icb = cc * 16;
        __syncthreads();
        for (int i = tid; i < 5184; i += 256) {
            int lic = i / 324, rem = i % 324, r = rem / 18, cl = rem % 18;
            int ih = ihb + r, iw = iwb + cl;
            float v = 0.f;
            if (ih >= 0 && ih < 128 && iw >= 0 && iw < 128)
                v = g_d1[(((long)b * 128 + icb + lic) * 128 + ih) * 128 + iw];
            p_s[i] = v;
        }
        for (int i = tid; i < 768; i += 256) {
            int o = i % 3, t = (i / 3) % 16, lic = i / 48;
            w_s[(lic * 16 + t) * 4 + o] = w[((long)o * 128 + icb + lic) * 16 + t];
        }
        __syncthreads();
        for (int lic = 0; lic < 16; lic++) {
            float x3[3][3];
#pragma unroll
            for (int r = 0; r < 3; r++)
#pragma unroll
                for (int c = 0; c < 3; c++)
                    x3[r][c] = p_s[lic * 324 + (qy + r) * 18 + qx + c];
#pragma unroll
            for (int kh = 0; kh < 4; kh++) {
#pragma unroll
                for (int kw = 0; kw < 4; kw++) {
                    const int RRh = (kh + (kh & 1)) >> 1;
                    const int RRw = (kw + (kw & 1)) >> 1;
                    float xv = x3[RRh][RRw];
                    const float* wp = w_s + (lic * 16 + kh * 4 + kw) * 4;
                    const int p = (kh & 1) * 2 + (kw & 1);
                    acc[p][0] += xv * wp[0];
                    acc[p][1] += xv * wp[1];
                    acc[p][2] += xv * wp[2];
                }
            }
        }
    }
    __syncthreads();
    float b0 = bias[0], b1 = bias[1], b2 = bias[2];
#pragma unroll
    for (int dy = 0; dy < 2; dy++)
#pragma unroll
        for (int dx = 0; dx < 2; dx++) {
            int y = 2 * qy + dy, xx = 2 * qx + dx;
            p_s[       y * 32 + xx] = acc[dy * 2 + dx][0] + b0;
            p_s[1024 + y * 32 + xx] = acc[dy * 2 + dx][1] + b1;
            p_s[2048 + y * 32 + xx] = acc[dy * 2 + dx][2] + b2;
        }
    __syncthreads();
    for (int i = tid; i < 3072; i += 256) {
        int o = i >> 10, rem = i & 1023, y = rem >> 5, xx = rem & 31;
        out[(((long)b * 3 + o) * 256 + y0 + y) * 256 + x0 + xx] = p_s[i];
    }
}

// =====================================================================
extern "C" void kernel_launch(void* const* d_in, const int* in_sizes, int n_in,
                              void* d_out, int out_size) {
    const float* x      = (const float*)d_in[0];
    const float* enc_w1 = (const float*)d_in[1];
    const float* enc_b1 = (const float*)d_in[2];
    const float* enc_w2 = (const float*)d_in[3];
    const float* enc_b2 = (const float*)d_in[4];
    const float* dec_w1 = (const float*)d_in[5];
    const float* dec_b1 = (const float*)d_in[6];
    const float* dec_w2 = (const float*)d_in[7];
    const float* dec_b2 = (const float*)d_in[8];
    const float* cb     = (const float*)d_in[9];
    float* out = (float*)d_out;

    cudaFuncSetAttribute(vq_argmin_kernel,
                         cudaFuncAttributeMaxDynamicSharedMemorySize, 133120);

    conv1_kernel   <<<dim3(8, 8, 32),  256>>>(x, enc_w1, enc_b1);
    conv2_kernel   <<<dim3(8, 8, 32),  256>>>(enc_w2, enc_b2);
    vq_argmin_kernel<<<512, 256, 133120>>>(cb);
    vq_gather_kernel<<<2048, 256>>>(cb);
    deconv1_kernel <<<dim3(8, 8, 256), 256>>>(dec_w1, dec_b1);
    deconv2_kernel <<<dim3(8, 8, 32),  256>>>(dec_w2, dec_b2, out);
}

// round 12
// speedup vs baseline: 1.6175x; 1.6175x over previous
#include <cuda_runtime.h>

typedef unsigned long long u64;

// ---------- packed f32x2 helpers (exact per-lane fp32, fast-math immune) ----------
__device__ __forceinline__ u64 bc2(float v) {
    u64 r; asm("mov.b64 %0, {%1,%1};" : "=l"(r) : "f"(v)); return r;
}
__device__ __forceinline__ u64 pk2(float lo, float hi) {
    u64 r; asm("mov.b64 %0, {%1,%2};" : "=l"(r) : "f"(lo), "f"(hi)); return r;
}
__device__ __forceinline__ void up2(u64 v, float& a, float& b) {
    asm("mov.b64 {%0,%1}, %2;" : "=f"(a), "=f"(b) : "l"(v));
}
__device__ __forceinline__ void fma2(u64& d, u64 a, u64 b) {
    asm("fma.rn.f32x2 %0, %1, %2, %0;" : "+l"(d) : "l"(a), "l"(b));
}

// ---------------- scratch (device globals: no allocations allowed) ----------------
__device__ float g_h1[67108864];   // [32,128,128,128] encoder hidden
__device__ float g_z [ 8388608];   // [32,64,64,64]    pre-quant latents
__device__ float g_zq[ 8388608];   // [32,64,64,64]    straight-through latents
__device__ float g_d1[67108864];   // [32,128,128,128] decoder hidden
__device__ int   g_idx[131072];    // [32,4096]        code indices

// =====================================================================
// conv1: x[32,3,256,256] -> h1[32,128,128,128], k4 s2 p1, bias + ReLU
// FFMA2: oc-pairs in lanes, weights transposed in smem for LDS.64.
// =====================================================================
__global__ __launch_bounds__(256) void conv1_kernel(const float* __restrict__ x,
                                                    const float* __restrict__ w,
                                                    const float* __restrict__ bias) {
    __shared__ float w_t[48 * 130];   // [j][oc], pitch 130 (bank spread)
    __shared__ float b_s[128];
    __shared__ float p_s[3 * 34 * 34];
    const int tid = threadIdx.x;
    const int b  = blockIdx.z;
    const int ty = blockIdx.y, tx = blockIdx.x;

    for (int i = tid; i < 6144; i += 256) {
        int oc = i / 48, j = i % 48;
        w_t[j * 130 + oc] = w[i];
    }
    if (tid < 128) b_s[tid] = bias[tid];

    const int iy0 = ty * 32 - 1, ix0 = tx * 32 - 1;
    for (int i = tid; i < 3468; i += 256) {
        int c = i / 1156, rem = i % 1156, r = rem / 34, cl = rem % 34;
        int iy = iy0 + r, ix = ix0 + cl;
        float v = 0.f;
        if (iy >= 0 && iy < 256 && ix >= 0 && ix < 256)
            v = x[((b * 3 + c) * 256 + iy) * 256 + ix];
        p_s[i] = v;
    }
    __syncthreads();

    const int lpy = tid >> 4, lpx = tid & 15;
    u64 xd[48];
#pragma unroll
    for (int c = 0; c < 3; c++)
#pragma unroll
        for (int kh = 0; kh < 4; kh++)
#pragma unroll
            for (int kw = 0; kw < 4; kw++)
                xd[c * 16 + kh * 4 + kw] =
                    bc2(p_s[c * 1156 + (2 * lpy + kh) * 34 + 2 * lpx + kw]);

    const int oy = ty * 16 + lpy, ox = tx * 16 + lpx;
    float* outp = &g_h1[(((long)b * 128) * 128 + oy) * 128 + ox];
    for (int oc = 0; oc < 128; oc += 4) {
        u64 a01 = pk2(b_s[oc], b_s[oc + 1]);
        u64 a23 = pk2(b_s[oc + 2], b_s[oc + 3]);
#pragma unroll
        for (int j = 0; j < 48; j++) {
            u64 w01 = *(const u64*)(w_t + j * 130 + oc);
            u64 w23 = *(const u64*)(w_t + j * 130 + oc + 2);
            fma2(a01, xd[j], w01);
            fma2(a23, xd[j], w23);
        }
        float r0, r1, r2, r3;
        up2(a01, r0, r1); up2(a23, r2, r3);
        outp[(long)(oc    ) * 16384] = fmaxf(r0, 0.f);
        outp[(long)(oc + 1) * 16384] = fmaxf(r1, 0.f);
        outp[(long)(oc + 2) * 16384] = fmaxf(r2, 0.f);
        outp[(long)(oc + 3) * 16384] = fmaxf(r3, 0.f);
    }
}

// =====================================================================
// conv2: h1 -> z[32,64,64,64], k4 s2 p1, bias. FFMA2.
// tile 8y x 16x, 64 oc; thread: 2x4 px quad-group x 4 oc (16 x2 accs).
// dynamic smem: p_s[8][18][36] | w_s[8192] (reused for staging) | b_s[64]
// =====================================================================
__global__ __launch_bounds__(256) void conv2_kernel(const float* __restrict__ w,
                                                    const float* __restrict__ bias) {
    extern __shared__ float sm2[];
    float* p_s = sm2;                 // 8*648 = 5184
    float* w_s = sm2 + 5184;          // 8192
    float* b_s = sm2 + 13376;         // 64
    const int tid = threadIdx.x;
    const int b   = blockIdx.z;
    const int oy0 = blockIdx.y * 8, ox0 = blockIdx.x * 16;
    const int iy0 = oy0 * 2 - 1, ix0 = ox0 * 2 - 1;
    if (tid < 64) b_s[tid] = bias[tid];

    const int ocq = tid & 15, pq = tid >> 4;
    const int gy = pq >> 2, gx = pq & 3;     // pixel group: rows gy*2+dy, cols gx*4+dx
    u64 A[8][2] = {};                         // [dy*4+dx][ocpair]

    for (int cc = 0; cc < 16; cc++) {
        const int icb = cc * 8;
        __syncthreads();
        for (int i = tid; i < 4896; i += 256) {
            int lic = i / 612, rem = i % 612, r = rem / 34, cl = rem % 34;
            int iy = iy0 + r, ix = ix0 + cl;
            float v = 0.f;
            if (iy >= 0 && iy < 128 && ix >= 0 && ix < 128)
                v = g_h1[(((long)b * 128 + icb + lic) * 128 + iy) * 128 + ix];
            p_s[lic * 648 + r * 36 + cl] = v;
        }
        for (int i = tid; i < 8192; i += 256) {
            int oc = i & 63, t = (i >> 6) & 15, lic = i >> 10;
            w_s[i] = w[((long)oc * 128 + icb + lic) * 16 + t];
        }
        __syncthreads();
        for (int lic = 0; lic < 8; lic++) {
            const float* pb = p_s + lic * 648;
#pragma unroll
            for (int kh = 0; kh < 4; kh++) {
                u64 xr[2][10];
#pragma unroll
                for (int dy = 0; dy < 2; dy++) {
                    const float* row = pb + (gy * 4 + 2 * dy + kh) * 36 + gx * 8;
                    float4 v0 = *(const float4*)row;
                    float4 v1 = *(const float4*)(row + 4);
                    xr[dy][0] = bc2(v0.x); xr[dy][1] = bc2(v0.y);
                    xr[dy][2] = bc2(v0.z); xr[dy][3] = bc2(v0.w);
                    xr[dy][4] = bc2(v1.x); xr[dy][5] = bc2(v1.y);
                    xr[dy][6] = bc2(v1.z); xr[dy][7] = bc2(v1.w);
                    xr[dy][8] = bc2(row[8]); xr[dy][9] = bc2(row[9]);
                }
#pragma unroll
                for (int kw = 0; kw < 4; kw++) {
                    const float* wp = w_s + (lic * 16 + kh * 4 + kw) * 64 + ocq * 4;
                    u64 w01 = *(const u64*)wp;
                    u64 w23 = *(const u64*)(wp + 2);
#pragma unroll
                    for (int dy = 0; dy < 2; dy++)
#pragma unroll
                        for (int dx = 0; dx < 4; dx++) {
                            u64 xv = xr[dy][2 * dx + kw];
                            fma2(A[dy * 4 + dx][0], xv, w01);
                            fma2(A[dy * 4 + dx][1], xv, w23);
                        }
                }
            }
        }
    }
    // stage into w_s (reused) for coalesced stores
    __syncthreads();
#pragma unroll
    for (int dy = 0; dy < 2; dy++)
#pragma unroll
        for (int dx = 0; dx < 4; dx++) {
            int y = gy * 2 + dy, xx = gx * 4 + dx;
            float r0, r1, r2, r3;
            up2(A[dy * 4 + dx][0], r0, r1);
            up2(A[dy * 4 + dx][1], r2, r3);
            int oc = ocq * 4;
            w_s[(oc    ) * 128 + y * 16 + xx] = r0 + b_s[oc    ];
            w_s[(oc + 1) * 128 + y * 16 + xx] = r1 + b_s[oc + 1];
            w_s[(oc + 2) * 128 + y * 16 + xx] = r2 + b_s[oc + 2];
            w_s[(oc + 3) * 128 + y * 16 + xx] = r3 + b_s[oc + 3];
        }
    __syncthreads();
    for (int i = tid; i < 8192; i += 256) {
        int oc = i >> 7, rem = i & 127, y = rem >> 4, xx = rem & 15;
        g_z[(((long)b * 64 + oc) * 64 + oy0 + y) * 64 + ox0 + xx] = w_s[i];
    }
}

// =====================================================================
// XLA-style row reduction of 64 squares (unchanged, bit-exact).
// =====================================================================
__device__ __forceinline__ float xla_sumsq64(const float* __restrict__ a) {
    float s[32];
#pragma unroll
    for (int j = 0; j < 32; j++)
        s[j] = __fadd_rn(__fmul_rn(a[j], a[j]), __fmul_rn(a[j + 32], a[j + 32]));
#pragma unroll
    for (int off = 16; off >= 1; off >>= 1)
#pragma unroll
        for (int j = 0; j < 16; j++)
            if (j < off) s[j] = __fadd_rn(s[j], s[j + off]);
    return s[0];
}

// =====================================================================
// VQ argmin: codebook TRANSPOSED in smem (pitch 520) so code-pairs load
// as LDS.64. Per-code FMA chain order (j = 0..63 sequential) and
// t = fl(fl(zz-2d)+cc) preserved bit-exactly vs the passing kernel.
// =====================================================================
__global__ __launch_bounds__(256) void vq_argmin_kernel(const float* __restrict__ cb) {
    extern __shared__ float sm[];
    float* cb_t = sm;            // [64][520]
    float* cn_s = sm + 33280;    // 512
    const int tid = threadIdx.x;
    for (int i = tid; i < 32768; i += 256) {
        int k = i >> 6, j = i & 63;
        cb_t[j * 520 + k] = cb[i];
    }
    __syncthreads();
    for (int k = tid; k < 512; k += 256) {
        float a[64];
#pragma unroll
        for (int j = 0; j < 64; j++) a[j] = cb_t[j * 520 + k];
        cn_s[k] = xla_sumsq64(a);
    }
    __syncthreads();

    const int v = blockIdx.x * 256 + tid;        // v = b*4096 + n
    const float* zp = g_z + (long)v * 64;
    float zr[64];
#pragma unroll
    for (int j = 0; j < 16; j++) {
        float4 t = *(const float4*)(zp + 4 * j);
        zr[4*j] = t.x; zr[4*j+1] = t.y; zr[4*j+2] = t.z; zr[4*j+3] = t.w;
    }
    const float zz = xla_sumsq64(zr);

    float best = 3.0e38f; int bi = 0;
    for (int k = 0; k < 512; k += 8) {
        u64 D0 = 0, D1 = 0, D2 = 0, D3 = 0;   // code pairs (k,k+1)..(k+6,k+7)
#pragma unroll
        for (int j = 0; j < 64; j++) {
            u64 zd = bc2(zr[j]);
            const u64* rp = (const u64*)(cb_t + j * 520 + k);
            fma2(D0, zd, rp[0]);
            fma2(D1, zd, rp[1]);
            fma2(D2, zd, rp[2]);
            fma2(D3, zd, rp[3]);
        }
        float d[8];
        up2(D0, d[0], d[1]); up2(D1, d[2], d[3]);
        up2(D2, d[4], d[5]); up2(D3, d[6], d[7]);
#pragma unroll
        for (int q = 0; q < 8; q++) {
            float t = __fadd_rn(__fadd_rn(zz, -__fmul_rn(2.f, d[q])), cn_s[k + q]);
            if (t < best) { best = t; bi = k + q; }   // first-min tie-break
        }
    }
    g_idx[v] = bi;
}

// =====================================================================
// scatter + straight-through (unchanged)
// =====================================================================
__global__ __launch_bounds__(256) void vq_gather_kernel(const float* __restrict__ cb) {
    const int tid = threadIdx.x;
    const int b = blockIdx.x >> 6, hh = blockIdx.x & 63;
    __shared__ int ids[64];
    if (tid < 64) ids[tid] = g_idx[b * 4096 + hh * 64 + tid];
    __syncthreads();
    const int ww = tid & 63, eg = tid >> 6;
    const int id = ids[ww];
#pragma unroll
    for (int it = 0; it < 16; it++) {
        int e = eg * 16 + it;
        long zo = (((long)b * 64 + e) * 64 + hh) * 64 + ww;
        float zv = g_z[zo];
        g_zq[zo] = __fadd_rn(zv, __fadd_rn(cb[id * 64 + e], -zv));
    }
}

// =====================================================================
// deconv1: zq -> d1[32,128,128,128], parity-decomposed, ReLU. FFMA2.
// tile 16y x 32x x 16 oc; thread: 2 input locs x 4 parities x 4 oc.
// =====================================================================
__global__ __launch_bounds__(256) void deconv1_kernel(const float* __restrict__ w,
                                                      const float* __restrict__ bias) {
    __shared__ float p_s[16 * 180];   // [ic16][10][18]
    __shared__ float sbuf[8320];      // w_s (4096) / staging (16*520)
    __shared__ float b_s[16];
    const int tid = threadIdx.x;
    const int bz = blockIdx.z;
    const int b = bz >> 3, OC0 = (bz & 7) * 16;
    const int y0 = blockIdx.y * 16, x0 = blockIdx.x * 32;
    const int ihb = (y0 >> 1) - 1, iwb = (x0 >> 1) - 1;
    if (tid < 16) b_s[tid] = bias[OC0 + tid];

    const int oq = tid & 3, pq = tid >> 2;
    const int ly = pq >> 3, lx = pq & 7;     // quad pair: (ly, 2lx) and (ly, 2lx+1)
    u64 A[2][4][2] = {};                      // [loc][parity][ocpair]

    for (int cc = 0; cc < 4; cc++) {
        const int icb = cc * 16;
        __syncthreads();
        for (int i = tid; i < 2880; i += 256) {
            int lic = i / 180, rem = i % 180, r = rem / 18, cl = rem % 18;
            int ih = ihb + r, iw = iwb + cl;
            float v = 0.f;
            if (ih >= 0 && ih < 64 && iw >= 0 && iw < 64)
                v = g_zq[(((long)b * 64 + icb + lic) * 64 + ih) * 64 + iw];
            p_s[i] = v;
        }
        for (int i = tid; i < 4096; i += 256) {
            int oc = i & 15, t = (i >> 4) & 15, lic = i >> 8;
            sbuf[i] = w[((long)(OC0 + oc) * 64 + icb + lic) * 16 + t];
        }
        __syncthreads();
        for (int lic = 0; lic < 16; lic++) {
            const float* pb = p_s + lic * 180 + ly * 18 + lx * 2;
            u64 xd[3][4];
#pragma unroll
            for (int r = 0; r < 3; r++) {
                float2 u = *(const float2*)(pb + r * 18);
                float2 v = *(const float2*)(pb + r * 18 + 2);
                xd[r][0] = bc2(u.x); xd[r][1] = bc2(u.y);
                xd[r][2] = bc2(v.x); xd[r][3] = bc2(v.y);
            }
#pragma unroll
            for (int kh = 0; kh < 4; kh++) {
#pragma unroll
                for (int kw = 0; kw < 4; kw++) {
                    const int RRh = (kh + (kh & 1)) >> 1;
                    const int RRw = (kw + (kw & 1)) >> 1;
                    const int p = (kh & 1) * 2 + (kw & 1);
                    const float* wp = sbuf + (lic * 16 + kh * 4 + kw) * 16 + oq * 4;
                    u64 w01 = *(const u64*)wp;
                    u64 w23 = *(const u64*)(wp + 2);
                    fma2(A[0][p][0], xd[RRh][RRw    ], w01);
                    fma2(A[0][p][1], xd[RRh][RRw    ], w23);
                    fma2(A[1][p][0], xd[RRh][RRw + 1], w01);
                    fma2(A[1][p][1], xd[RRh][RRw + 1], w23);
                }
            }
        }
    }
    __syncthreads();
#pragma unroll
    for (int loc = 0; loc < 2; loc++)
#pragma unroll
        for (int dy = 0; dy < 2; dy++)
#pragma unroll
            for (int dx = 0; dx < 2; dx++) {
                int p = dy * 2 + dx;
                int y = 2 * ly + dy, xx = 2 * (2 * lx + loc) + dx;
                float r0, r1, r2, r3;
                up2(A[loc][p][0], r0, r1);
                up2(A[loc][p][1], r2, r3);
                int oc = oq * 4;
                sbuf[(oc    ) * 520 + y * 32 + xx] = fmaxf(r0 + b_s[oc    ], 0.f);
                sbuf[(oc + 1) * 520 + y * 32 + xx] = fmaxf(r1 + b_s[oc + 1], 0.f);
                sbuf[(oc + 2) * 520 + y * 32 + xx] = fmaxf(r2 + b_s[oc + 2], 0.f);
                sbuf[(oc + 3) * 520 + y * 32 + xx] = fmaxf(r3 + b_s[oc + 3], 0.f);
            }
    __syncthreads();
    for (int i = tid; i < 8192; i += 256) {
        int oc = i >> 9, rem = i & 511, y = rem >> 5, xx = rem & 31;
        g_d1[(((long)b * 128 + OC0 + oc) * 128 + y0 + y) * 128 + x0 + xx] =
            sbuf[oc * 520 + y * 32 + xx];
    }
}

// =====================================================================
// deconv2: d1 -> out[32,3,256,256]. FFMA2 on oc(0,1) + scalar oc 2.
// tile 32y x 64x; thread: 2 input locs x 4 parities x 3 oc.
// =====================================================================
__global__ __launch_bounds__(256) void deconv2_kernel(const float* __restrict__ w,
                                                      const float* __restrict__ bias,
                                                      float* __restrict__ out) {
    __shared__ float p_s[16 * 612];   // [ic16][18][34]; reused for staging
    __shared__ float w_s[1024];       // [(lic*16+t)][4] (3 used)
    const int tid = threadIdx.x;
    const int b = blockIdx.z;
    const int y0 = blockIdx.y * 32, x0 = blockIdx.x * 64;
    const int ihb = (y0 >> 1) - 1, iwb = (x0 >> 1) - 1;
    const int ly = tid >> 4, lx = tid & 15;  // quad pair (ly, 2lx), (ly, 2lx+1)

    u64   A01[2][4] = {};
    float A2 [2][4] = {};

    for (int cc = 0; cc < 8; cc++) {
        const int icb = cc * 16;
        __syncthreads();
        for (int i = tid; i < 9792; i += 256) {
            int lic = i / 612, rem = i % 612, r = rem / 34, cl = rem % 34;
            int ih = ihb + r, iw = iwb + cl;
            float v = 0.f;
            if (ih >= 0 && ih < 128 && iw >= 0 && iw < 128)
                v = g_d1[(((long)b * 128 + icb + lic) * 128 + ih) * 128 + iw];
            p_s[i] = v;
        }
        for (int i = tid; i < 768; i += 256) {
            int o = i % 3, t = (i / 3) % 16, lic = i / 48;
            w_s[(lic * 16 + t) * 4 + o] = w[((long)o * 128 + icb + lic) * 16 + t];
        }
        __syncthreads();
        for (int lic = 0; lic < 16; lic++) {
            const float* pb = p_s + lic * 612 + ly * 34 + lx * 2;
            float xs[3][4]; u64 xd[3][4];
#pragma unroll
            for (int r = 0; r < 3; r++) {
                float2 u = *(const float2*)(pb + r * 34);
                float2 v = *(const float2*)(pb + r * 34 + 2);
                xs[r][0] = u.x; xs[r][1] = u.y; xs[r][2] = v.x; xs[r][3] = v.y;
                xd[r][0] = bc2(u.x); xd[r][1] = bc2(u.y);
                xd[r][2] = bc2(v.x); xd[r][3] = bc2(v.y);
            }
#pragma unroll
            for (int kh = 0; kh < 4; kh++) {
#pragma unroll
                for (int kw = 0; kw < 4; kw++) {
                    const int RRh = (kh + (kh & 1)) >> 1;
                    const int RRw = (kw + (kw & 1)) >> 1;
                    const int p = (kh & 1) * 2 + (kw & 1);
                    const float* wp = w_s + (lic * 16 + kh * 4 + kw) * 4;
                    u64 w01 = *(const u64*)wp;
                    float w2 = wp[2];
                    fma2(A01[0][p], xd[RRh][RRw    ], w01);
                    fma2(A01[1][p], xd[RRh][RRw + 1], w01);
                    A2[0][p] = __fmaf_rn(xs[RRh][RRw    ], w2, A2[0][p]);
                    A2[1][p] = __fmaf_rn(xs[RRh][RRw + 1], w2, A2[1][p]);
                }
            }
        }
    }
    __syncthreads();
    const float b0 = bias[0], b1 = bias[1], b2 = bias[2];
#pragma unroll
    for (int loc = 0; loc < 2; loc++)
#pragma unroll
        for (int dy = 0; dy < 2; dy++)
#pragma unroll
            for (int dx = 0; dx < 2; dx++) {
                int p = dy * 2 + dx;
                int y = 2 * ly + dy, xx = 2 * (2 * lx + loc) + dx;
                float r0, r1; up2(A01[loc][p], r0, r1);
                p_s[           y * 64 + xx] = r0 + b0;
                p_s[2080     + y * 64 + xx] = r1 + b1;
                p_s[2 * 2080 + y * 64 + xx] = A2[loc][p] + b2;
            }
    __syncthreads();
    for (int i = tid; i < 6144; i += 256) {
        int o = i >> 11, rem = i & 2047, y = rem >> 6, xx = rem & 63;
        out[(((long)b * 3 + o) * 256 + y0 + y) * 256 + x0 + xx] =
            p_s[o * 2080 + y * 64 + xx];
    }
}

// =====================================================================
extern "C" void kernel_launch(void* const* d_in, const int* in_sizes, int n_in,
                              void* d_out, int out_size) {
    const float* x      = (const float*)d_in[0];
    const float* enc_w1 = (const float*)d_in[1];
    const float* enc_b1 = (const float*)d_in[2];
    const float* enc_w2 = (const float*)d_in[3];
    const float* enc_b2 = (const float*)d_in[4];
    const float* dec_w1 = (const float*)d_in[5];
    const float* dec_b1 = (const float*)d_in[6];
    const float* dec_w2 = (const float*)d_in[7];
    const float* dec_b2 = (const float*)d_in[8];
    const float* cb     = (const float*)d_in[9];
    float* out = (float*)d_out;

    cudaFuncSetAttribute(vq_argmin_kernel,
                         cudaFuncAttributeMaxDynamicSharedMemorySize, 135168);
    cudaFuncSetAttribute(conv2_kernel,
                         cudaFuncAttributeMaxDynamicSharedMemorySize, 53760);

    conv1_kernel    <<<dim3(8, 8, 32),  256>>>(x, enc_w1, enc_b1);
    conv2_kernel    <<<dim3(4, 8, 32),  256, 53760>>>(enc_w2, enc_b2);
    vq_argmin_kernel<<<512, 256, 135168>>>(cb);
    vq_gather_kernel<<<2048, 256>>>(cb);
    deconv1_kernel  <<<dim3(4, 8, 256), 256>>>(dec_w1, dec_b1);
    deconv2_kernel  <<<dim3(4, 8, 32),  256>>>(dec_w2, dec_b2, out);
}